// round 15
// baseline (speedup 1.0000x reference)
#include <cuda_runtime.h>
#include <cuda_fp16.h>
#include <math.h>

#define MTOK   73728
#define CDIM   192
#define NHEAD  6
#define HD     32
#define NTOK   144
#define NWIN   512
#define TWIN   32
#define NWW    16
#define NB     3312
#define QKVN   576
#define FFN    768

// fp32 buffers (residual stream, bias table)
__device__ float  g_x   [(size_t)MTOK * CDIM];
__device__ float  g_bm  [(size_t)2 * TWIN * NHEAD * NTOK * NTOK];
// f16 activation buffers
__device__ __half g_xh16 [(size_t)MTOK * CDIM];
__device__ __half g_qkv16[(size_t)MTOK * QKVN];   // QKV out; also MLP-down out
__device__ __half g_ao16 [(size_t)MTOK * CDIM];
__device__ __half g_h16  [(size_t)MTOK * FFN];    // MLP hidden; also proj out
// f16 transposed weights [N][K]: qkv | proj | w1 | w2 (both layers)
#define WQ_OFF 0
#define WP_OFF 221184
#define W1_OFF 294912
#define W2_OFF 589824
__device__ __half g_wt16[884736];

// ---------------------------------------------------------------------------
// helpers
// ---------------------------------------------------------------------------
__device__ __forceinline__ void mma_f16(float* d, const unsigned* a, const unsigned* b) {
    asm volatile(
        "mma.sync.aligned.m16n8k16.row.col.f32.f16.f16.f32 "
        "{%0,%1,%2,%3}, {%4,%5,%6,%7}, {%8,%9}, {%0,%1,%2,%3};\n"
        : "+f"(d[0]), "+f"(d[1]), "+f"(d[2]), "+f"(d[3])
        : "r"(a[0]), "r"(a[1]), "r"(a[2]), "r"(a[3]),
          "r"(b[0]), "r"(b[1]));
}

__device__ __forceinline__ void ldsm_x4(unsigned& r0, unsigned& r1,
                                        unsigned& r2, unsigned& r3, unsigned a) {
    asm volatile("ldmatrix.sync.aligned.m8n8.x4.shared.b16 {%0,%1,%2,%3}, [%4];"
                 : "=r"(r0), "=r"(r1), "=r"(r2), "=r"(r3) : "r"(a));
}
#define STSM_X2(addr, r0, r1) \
    asm volatile("stmatrix.sync.aligned.m8n8.x2.shared.b16 [%0], {%1,%2};" \
                 :: "r"(addr), "r"(r0), "r"(r1))

__device__ __forceinline__ unsigned h2u(float a, float b) {
    __half2 h = __floats2half2_rn(a, b);
    return reinterpret_cast<unsigned&>(h);
}

__device__ __forceinline__ unsigned smaddr(const void* p) {
    return (unsigned)__cvta_generic_to_shared(p);
}
#define CPA16(dst, src) asm volatile("cp.async.cg.shared.global [%0], [%1], 16;" :: "r"(dst), "l"(src))
#define CPCOMMIT()      asm volatile("cp.async.commit_group;")
#define CPWAIT1()       asm volatile("cp.async.wait_group 1;")
#define CPWAIT0()       asm volatile("cp.async.wait_group 0;")

__device__ __forceinline__ float gelu_exact(float v) {
    return 0.5f * v * (1.0f + erff(v * 0.70710678118654752f));
}

// ---------------------------------------------------------------------------
// Batched prep: all 8 weight transposes (fp32 [K][N] -> f16 [N][K]); 864 tiles.
// ---------------------------------------------------------------------------
__global__ void transpose_all_kernel(const float* __restrict__ qkv_w,
                                     const float* __restrict__ proj_w,
                                     const float* __restrict__ w1,
                                     const float* __restrict__ w2) {
    __shared__ float t[32][33];
    int idx = blockIdx.x;
    const int layer = idx / 432;
    int r = idx % 432;

    const float* src;
    __half* dst;
    int K, N, kt, nt;
    if (r < 108) {
        K = CDIM; N = QKVN;
        kt = r / 18; nt = r % 18;
        src = qkv_w + (size_t)layer * CDIM * QKVN;
        dst = g_wt16 + WQ_OFF + (size_t)layer * CDIM * QKVN;
    } else if (r < 144) {
        r -= 108; K = CDIM; N = CDIM;
        kt = r / 6; nt = r % 6;
        src = proj_w + (size_t)layer * CDIM * CDIM;
        dst = g_wt16 + WP_OFF + (size_t)layer * CDIM * CDIM;
    } else if (r < 288) {
        r -= 144; K = CDIM; N = FFN;
        kt = r / 24; nt = r % 24;
        src = w1 + (size_t)layer * CDIM * FFN;
        dst = g_wt16 + W1_OFF + (size_t)layer * CDIM * FFN;
    } else {
        r -= 288; K = FFN; N = CDIM;
        kt = r / 6; nt = r % 6;
        src = w2 + (size_t)layer * FFN * CDIM;
        dst = g_wt16 + W2_OFF + (size_t)layer * FFN * CDIM;
    }

    const int n0 = nt * 32, k0 = kt * 32;
    const int tx = threadIdx.x, ty = threadIdx.y;
    #pragma unroll
    for (int i = 0; i < 32; i += 8)
        t[ty + i][tx] = src[(size_t)(k0 + ty + i) * N + n0 + tx];
    __syncthreads();
    #pragma unroll
    for (int i = 0; i < 32; i += 8)
        dst[(size_t)(n0 + ty + i) * K + k0 + tx] = __float2half_rn(t[tx][ty + i]);
}

__global__ void cvt_f16_kernel(const float* __restrict__ src,
                               __half* __restrict__ dst, int n) {
    int i = blockIdx.x * blockDim.x + threadIdx.x;
    if (i < n) dst[i] = __float2half_rn(src[i]);
}

// ---------------------------------------------------------------------------
// Dense (relative-position bias + shift mask)
// ---------------------------------------------------------------------------
__global__ void biasmask_kernel(const float* __restrict__ table) {
    size_t idx = (size_t)blockIdx.x * blockDim.x + threadIdx.x;
    size_t total = (size_t)2 * TWIN * NHEAD * NTOK * NTOK;
    if (idx >= total) return;
    int m = idx % NTOK; size_t r = idx / NTOK;
    int n = r % NTOK;   r /= NTOK;
    int head = r % NHEAD; r /= NHEAD;
    int t = r % TWIN;   int L = (int)(r / TWIN);
    int z1 = n / 72, h1 = (n % 72) / 12, w1 = n % 12;
    int z2 = m / 72, h2 = (m % 72) / 12, w2 = m % 12;
    int pos = 828 * (z1 + 2 * z2) + 23 * (h1 + 6 * h2) + (w1 - w2 + 11);
    float v = table[(((size_t)L * NB + pos) * TWIN + t) * NHEAD + head];
    if (L == 1) {
        int tz = t / 8, th = t % 8;
        int idn = (((tz * 2 + z1) >= 1) ? 2 : 0) + (((th * 6 + h1) >= 3) ? 1 : 0);
        int idm = (((tz * 2 + z2) >= 1) ? 2 : 0) + (((th * 6 + h2) >= 3) ? 1 : 0);
        if (idn != idm) v += -10000.0f;
    }
    g_bm[idx] = v;
}

// ---------------------------------------------------------------------------
// Resident-A f16 GEMM for K=192: the whole A tile (128x192) stays in smem;
// block loops over 64-wide N-chunks with a double-buffered FULL-K B tile.
// Mainloop per chunk: 12 unrolled k16-steps, ZERO barriers/waits inside.
// One __syncthreads per N-chunk (B buffer swap). 256 thr / 8 warps (4m x 2n),
// warp tile 32x32. Stride 200 halves -> ldmatrix conflict-free (100r mod 32
// = 4r covers all banks). smem 102,400 B -> 2 blocks/SM.
// ---------------------------------------------------------------------------
#define RA_S    200
#define RA_ABUF (128 * RA_S)            // halves
#define RA_BBUF (64 * RA_S)             // halves
#define RESA_SMEM ((RA_ABUF + 2 * RA_BBUF) * 2)   // 102400 B

template <int EPI, int GATHER>
__global__ void __launch_bounds__(256, 2)
hgemm_resA_kernel(const __half* __restrict__ A,
                  const __half* __restrict__ B,
                  const float* __restrict__ bias,
                  __half* __restrict__ C16,
                  int NBLK, int Nn, int rolled) {
    extern __shared__ __half rsm[];
    __half* As = rsm;                       // [128][200]
    __half* Bs = rsm + RA_ABUF;             // 2 x [64][200]

    const int tid  = threadIdx.x;
    const int lane = tid & 31;
    const int wid  = tid >> 5;
    const int wm   = wid >> 1;
    const int wn   = wid & 1;
    const int g    = lane >> 2;
    const int tg   = lane & 3;
    const int m0   = blockIdx.x * 128;

    const unsigned lrow = lane & 7;
    const unsigned lsel = (lane >> 3) & 1;
    const unsigned lhi  = lane >> 4;
    const unsigned aoff = ((lrow + lsel * 8) * RA_S + lhi * 8) * 2;
    const unsigned boff = ((lrow + lhi * 8) * RA_S + lsel * 8) * 2;

    // copy roles: A 2 thr/row, 12 x 16B; B 4 thr/row, 6 x 16B
    const int arow = tid >> 1;
    const int ah0  = (tid & 1) * 96;
    const int brow = tid >> 2;
    const int bq0  = (tid & 3) * 48;

    size_t arowp;
    {
        int r = m0 + arow;
        if (GATHER) {
            int n = r % NTOK, win = r / NTOK;
            int l = win % NWW, t = win / NWW;
            int tz = t / 8, th = t % 8;
            int z1 = n / 72, h1 = (n % 72) / 12, w1 = n % 12;
            int zr = tz * 2 + z1, hr = th * 6 + h1, wr = l * 12 + w1;
            int z, hh, ww;
            if (rolled) { z = (zr + 7) & 7; hh = (hr + 45) % 48; ww = (wr + 186) % 192; }
            else        { z = zr; hh = hr; ww = wr; }
            arowp = ((size_t)z * 48 + hh) * 192 + ww;
        } else {
            arowp = (size_t)r;
        }
    }
    const __half* aSrc = A + arowp * CDIM + ah0;
    const unsigned adst = smaddr(As) + (unsigned)(arow * RA_S + ah0) * 2;
    const unsigned bdst0 = (unsigned)(brow * RA_S + bq0) * 2;

    // prologue: whole A (group) + B chunk 0 (group)
    #pragma unroll
    for (int j = 0; j < 12; j++) CPA16(adst + j * 16, aSrc + j * 8);
    CPCOMMIT();
    {
        const __half* bS = B + (size_t)brow * CDIM + bq0;
        const unsigned bb = smaddr(Bs);
        #pragma unroll
        for (int j = 0; j < 6; j++) CPA16(bb + bdst0 + j * 16, bS + j * 8);
    }
    CPCOMMIT();
    CPWAIT0();
    __syncthreads();

    const unsigned aB = smaddr(As) + (unsigned)(wm * 32 * RA_S) * 2 + aoff;

    for (int nb = 0; nb < NBLK; nb++) {
        // prefetch next B chunk into the other buffer
        if (nb + 1 < NBLK) {
            const __half* bS = B + (size_t)((nb + 1) * 64 + brow) * CDIM + bq0;
            const unsigned bb = smaddr(Bs + ((nb + 1) & 1) * RA_BBUF);
            #pragma unroll
            for (int j = 0; j < 6; j++) CPA16(bb + bdst0 + j * 16, bS + j * 8);
        }
        CPCOMMIT();

        const unsigned bB = smaddr(Bs + (nb & 1) * RA_BBUF) +
                            (unsigned)(wn * 32 * RA_S) * 2 + boff;
        float acc[2][4][4];
        #pragma unroll
        for (int mt = 0; mt < 2; mt++)
            #pragma unroll
            for (int nt = 0; nt < 4; nt++)
                #pragma unroll
                for (int i = 0; i < 4; i++) acc[mt][nt][i] = 0.0f;

        #pragma unroll
        for (int kk = 0; kk < 12; kk++) {
            unsigned af[2][4], bf[4][2];
            ldsm_x4(af[0][0], af[0][1], af[0][2], af[0][3], aB + kk * 32);
            ldsm_x4(af[1][0], af[1][1], af[1][2], af[1][3], aB + 16 * RA_S * 2 + kk * 32);
            ldsm_x4(bf[0][0], bf[0][1], bf[1][0], bf[1][1], bB + kk * 32);
            ldsm_x4(bf[2][0], bf[2][1], bf[3][0], bf[3][1], bB + 16 * RA_S * 2 + kk * 32);
            #pragma unroll
            for (int mt = 0; mt < 2; mt++)
                #pragma unroll
                for (int nt = 0; nt < 4; nt++)
                    mma_f16(acc[mt][nt], af[mt], bf[nt]);
        }

        // epilogue for this N-chunk
        #pragma unroll
        for (int mt = 0; mt < 2; mt++) {
            int r0 = m0 + wm * 32 + mt * 16 + g;
            #pragma unroll
            for (int nt = 0; nt < 4; nt++) {
                int c = nb * 64 + wn * 32 + nt * 8 + tg * 2;
                float b0 = bias[c], b1 = bias[c + 1];
                float v0 = acc[mt][nt][0] + b0;
                float v1 = acc[mt][nt][1] + b1;
                float v2 = acc[mt][nt][2] + b0;
                float v3 = acc[mt][nt][3] + b1;
                if (EPI == 1) {
                    v0 = gelu_exact(v0); v1 = gelu_exact(v1);
                    v2 = gelu_exact(v2); v3 = gelu_exact(v3);
                }
                *reinterpret_cast<__half2*>(C16 + (size_t)r0 * Nn + c) =
                    __floats2half2_rn(v0, v1);
                *reinterpret_cast<__half2*>(C16 + (size_t)(r0 + 8) * Nn + c) =
                    __floats2half2_rn(v2, v3);
            }
        }

        if (nb + 1 < NBLK) {
            CPWAIT0();
            __syncthreads();
        }
    }
}

// ---------------------------------------------------------------------------
// Streaming f16 GEMM (R11, proven) — used for MLP-down (K=768) only.
// ---------------------------------------------------------------------------
#define ASTG16 (128 * 40)
#define BSTG16 (64 * 40)
#define GEMM_SMEM16 ((3 * ASTG16 + 3 * BSTG16) * 2)   // 46080 B

template <int EPI>
__global__ void __launch_bounds__(256, 3)
hgemm_kernel(const __half* __restrict__ A,
             const __half* __restrict__ B,
             const float* __restrict__ bias,
             __half* __restrict__ C16,
             int K, int Nn) {
    extern __shared__ __half hsm[];
    __half* As = hsm;
    __half* Bs = hsm + 3 * ASTG16;

    const int tid  = threadIdx.x;
    const int lane = tid & 31;
    const int wid  = tid >> 5;
    const int wm   = wid >> 1;
    const int wn   = wid & 1;
    const int g    = lane >> 2;
    const int tg   = lane & 3;
    const int m0   = blockIdx.y * 128;
    const int n0   = blockIdx.x * 64;

    const unsigned lrow = lane & 7;
    const unsigned lsel = (lane >> 3) & 1;
    const unsigned lhi  = lane >> 4;
    const unsigned aoff = ((lrow + lsel * 8) * 40 + lhi * 8) * 2;
    const unsigned boff = ((lrow + lhi * 8) * 40 + lsel * 8) * 2;

    const int arow = tid >> 1;
    const int ac0  = (tid & 1) * 2;
    const int brow = tid >> 2;
    const int bchk = tid & 3;

    const __half* aSrc = A + (size_t)(m0 + arow) * K;
    const __half* bSrc = B + (size_t)(n0 + brow) * K;

    float acc[2][4][4];
    #pragma unroll
    for (int mt = 0; mt < 2; mt++)
        #pragma unroll
        for (int nt = 0; nt < 4; nt++)
            #pragma unroll
            for (int i = 0; i < 4; i++) acc[mt][nt][i] = 0.0f;

    #pragma unroll
    for (int s = 0; s < 2; s++) {
        __half* as = As + s * ASTG16;
        __half* bs = Bs + s * BSTG16;
        const int k0 = s * 32;
        #pragma unroll
        for (int j = 0; j < 2; j++)
            CPA16(smaddr(as + arow * 40 + (ac0 + j) * 8), aSrc + k0 + (ac0 + j) * 8);
        CPA16(smaddr(bs + brow * 40 + bchk * 8), bSrc + k0 + bchk * 8);
        CPCOMMIT();
    }

    const int iters = K >> 5;
    int cur = 0;
    for (int it = 0; it < iters; it++) {
        CPWAIT1();
        __syncthreads();

        const int k0n = (it + 2) << 5;
        if (k0n < K) {
            const int stg = (cur + 2) % 3;
            __half* asw = As + stg * ASTG16;
            __half* bsw = Bs + stg * BSTG16;
            #pragma unroll
            for (int j = 0; j < 2; j++)
                CPA16(smaddr(asw + arow * 40 + (ac0 + j) * 8), aSrc + k0n + (ac0 + j) * 8);
            CPA16(smaddr(bsw + brow * 40 + bchk * 8), bSrc + k0n + bchk * 8);
        }
        CPCOMMIT();

        const __half* as = As + cur * ASTG16;
        const __half* bs = Bs + cur * BSTG16;
        const unsigned aB = smaddr(as) + (unsigned)(wm * 32 * 40) * 2 + aoff;
        const unsigned bB = smaddr(bs) + (unsigned)(wn * 32 * 40) * 2 + boff;
        #pragma unroll
        for (int kk2 = 0; kk2 < 2; kk2++) {
            unsigned af[2][4], bf[4][2];
            ldsm_x4(af[0][0], af[0][1], af[0][2], af[0][3], aB + kk2 * 32);
            ldsm_x4(af[1][0], af[1][1], af[1][2], af[1][3], aB + 1280 + kk2 * 32);
            ldsm_x4(bf[0][0], bf[0][1], bf[1][0], bf[1][1], bB + kk2 * 32);
            ldsm_x4(bf[2][0], bf[2][1], bf[3][0], bf[3][1], bB + 1280 + kk2 * 32);
            #pragma unroll
            for (int mt = 0; mt < 2; mt++)
                #pragma unroll
                for (int nt = 0; nt < 4; nt++)
                    mma_f16(acc[mt][nt], af[mt], bf[nt]);
        }
        cur = (cur + 1) % 3;
    }

    #pragma unroll
    for (int mt = 0; mt < 2; mt++) {
        int r0 = m0 + wm * 32 + mt * 16 + g;
        #pragma unroll
        for (int nt = 0; nt < 4; nt++) {
            int c = n0 + wn * 32 + nt * 8 + tg * 2;
            float b0 = bias[c], b1 = bias[c + 1];
            float v0 = acc[mt][nt][0] + b0;
            float v1 = acc[mt][nt][1] + b1;
            float v2 = acc[mt][nt][2] + b0;
            float v3 = acc[mt][nt][3] + b1;
            if (EPI == 1) {
                v0 = gelu_exact(v0); v1 = gelu_exact(v1);
                v2 = gelu_exact(v2); v3 = gelu_exact(v3);
            }
            *reinterpret_cast<__half2*>(C16 + (size_t)r0 * Nn + c) =
                __floats2half2_rn(v0, v1);
            *reinterpret_cast<__half2*>(C16 + (size_t)(r0 + 8) * Nn + c) =
                __floats2half2_rn(v2, v3);
        }
    }
}

// ---------------------------------------------------------------------------
// f16 tensor-core window attention (unchanged — proven bit-exact)
// ---------------------------------------------------------------------------
#define KS16_S 40
#define VT16_S 152
#define SCR16_S 152
#define ATTN_SMEM16 ((NTOK * KS16_S + HD * VT16_S + 4 * 16 * SCR16_S) * 2)

__global__ void __launch_bounds__(128, 3) attn_f16_kernel(int L) {
    const int win  = blockIdx.x;
    const int head = blockIdx.y;
    const int t    = win >> 4;
    extern __shared__ __half smh[];
    __half* ks  = smh;
    __half* vsT = ks + NTOK * KS16_S;
    __half* scr = vsT + HD * VT16_S;

    const int tid  = threadIdx.x;
    const int lane = tid & 31;
    const int wid  = tid >> 5;
    const int g    = lane >> 2;
    const int tg   = lane & 3;

    const unsigned lrow = lane & 7;
    const unsigned lsel = (lane >> 3) & 1;
    const unsigned lhi  = lane >> 4;
    const unsigned kboff = ((lrow + lhi * 8) * KS16_S + lsel * 8) * 2;
    const unsigned paoff = ((lrow + lsel * 8) * SCR16_S + lhi * 8) * 2;
    const unsigned vboff = ((lrow + lhi * 8) * VT16_S + lsel * 8) * 2;

    const __half* base = g_qkv16 + (size_t)win * NTOK * QKVN;
    const int hc = head * HD;
    for (int idx = tid; idx < NTOK * 4; idx += 128) {
        int row = idx >> 2, c = idx & 3;
        *reinterpret_cast<uint4*>(&ks[row * KS16_S + c * 8]) =
            *reinterpret_cast<const uint4*>(base + (size_t)row * QKVN + CDIM + hc + c * 8);
        uint4 v4 = *reinterpret_cast<const uint4*>(base + (size_t)row * QKVN + 2 * CDIM + hc + c * 8);
        const __half* hv = reinterpret_cast<const __half*>(&v4);
        #pragma unroll
        for (int j = 0; j < 8; j++)
            vsT[(c * 8 + j) * VT16_S + row] = hv[j];
    }
    __syncthreads();

    const float* bmb = g_bm + (((size_t)L * TWIN + t) * NHEAD + head) * NTOK * NTOK;
    __half* wscr = scr + wid * 16 * SCR16_S;
    const unsigned kbase  = smaddr(ks) + kboff;
    const unsigned pbase  = smaddr(wscr) + paoff;
    const unsigned vbase  = smaddr(vsT) + vboff;
    const unsigned stbase = smaddr(wscr) + (unsigned)((lane & 15) * SCR16_S) * 2;
    const float sc = 0.17677669529663687f;

    for (int mt = wid; mt < 9; mt += 4) {
        const int rb = mt * 16;

        const __half* qA = g_qkv16 + (size_t)(win * NTOK + rb + g) * QKVN + hc;
        const __half* qB = g_qkv16 + (size_t)(win * NTOK + rb + 8 + g) * QKVN + hc;
        unsigned aq[2][4];
        #pragma unroll
        for (int kk2 = 0; kk2 < 2; kk2++) {
            const int kk = kk2 * 16 + 2 * tg;
            aq[kk2][0] = *reinterpret_cast<const unsigned*>(qA + kk);
            aq[kk2][1] = *reinterpret_cast<const unsigned*>(qB + kk);
            aq[kk2][2] = *reinterpret_cast<const unsigned*>(qA + kk + 8);
            aq[kk2][3] = *reinterpret_cast<const unsigned*>(qB + kk + 8);
        }

        float sacc[18][4];
        #pragma unroll
        for (int ntp = 0; ntp < 9; ntp++) {
            float* s0 = sacc[2 * ntp];
            float* s1 = sacc[2 * ntp + 1];
            #pragma unroll
            for (int i = 0; i < 4; i++) { s0[i] = 0.0f; s1[i] = 0.0f; }
            #pragma unroll
            for (int kk2 = 0; kk2 < 2; kk2++) {
                unsigned b0, b1, b2, b3;
                ldsm_x4(b0, b1, b2, b3, kbase + ntp * (16 * KS16_S * 2) + kk2 * 32);
                unsigned bfa[2] = {b0, b1}, bfb[2] = {b2, b3};
                mma_f16(s0, aq[kk2], bfa);
                mma_f16(s1, aq[kk2], bfb);
            }
            #pragma unroll
            for (int h = 0; h < 2; h++) {
                float* sv = h ? s1 : s0;
                const int cb = (2 * ntp + h) * 8;
                const float2 bA = *reinterpret_cast<const float2*>(
                    bmb + (size_t)(rb + g) * NTOK + cb + tg * 2);
                const float2 bB = *reinterpret_cast<const float2*>(
                    bmb + (size_t)(rb + 8 + g) * NTOK + cb + tg * 2);
                sv[0] = fmaf(sv[0], sc, bA.x);
                sv[1] = fmaf(sv[1], sc, bA.y);
                sv[2] = fmaf(sv[2], sc, bB.x);
                sv[3] = fmaf(sv[3], sc, bB.y);
            }
        }

        float mxA = -1e30f, mxB = -1e30f;
        #pragma unroll
        for (int nt = 0; nt < 18; nt++) {
            mxA = fmaxf(mxA, fmaxf(sacc[nt][0], sacc[nt][1]));
            mxB = fmaxf(mxB, fmaxf(sacc[nt][2], sacc[nt][3]));
        }
        #pragma unroll
        for (int o = 1; o <= 2; o <<= 1) {
            mxA = fmaxf(mxA, __shfl_xor_sync(0xFFFFFFFFu, mxA, o));
            mxB = fmaxf(mxB, __shfl_xor_sync(0xFFFFFFFFu, mxB, o));
        }
        float smA = 0.0f, smB = 0.0f;
        #pragma unroll
        for (int nt = 0; nt < 18; nt++) {
            sacc[nt][0] = __expf(sacc[nt][0] - mxA);
            sacc[nt][1] = __expf(sacc[nt][1] - mxA);
            sacc[nt][2] = __expf(sacc[nt][2] - mxB);
            sacc[nt][3] = __expf(sacc[nt][3] - mxB);
            smA += sacc[nt][0] + sacc[nt][1];
            smB += sacc[nt][2] + sacc[nt][3];
        }
        #pragma unroll
        for (int o = 1; o <= 2; o <<= 1) {
            smA += __shfl_xor_sync(0xFFFFFFFFu, smA, o);
            smB += __shfl_xor_sync(0xFFFFFFFFu, smB, o);
        }
        const float invA = 1.0f / smA;
        const float invB = 1.0f / smB;

        #pragma unroll
        for (int nt = 0; nt < 18; nt++) {
            unsigned r0 = h2u(sacc[nt][0], sacc[nt][1]);
            unsigned r1 = h2u(sacc[nt][2], sacc[nt][3]);
            STSM_X2(stbase + nt * 16, r0, r1);
        }
        __syncwarp();

        float oacc[4][4];
        #pragma unroll
        for (int nt = 0; nt < 4; nt++)
            oacc[nt][0] = oacc[nt][1] = oacc[nt][2] = oacc[nt][3] = 0.0f;
        #pragma unroll
        for (int kk = 0; kk < 9; kk++) {
            unsigned ap[4];
            ldsm_x4(ap[0], ap[1], ap[2], ap[3], pbase + kk * 32);
            unsigned b0, b1, b2, b3, c0, c1, c2, c3;
            ldsm_x4(b0, b1, b2, b3, vbase + kk * 32);
            ldsm_x4(c0, c1, c2, c3, vbase + (16 * VT16_S * 2) + kk * 32);
            { unsigned bf[2] = {b0, b1}; mma_f16(oacc[0], ap, bf); }
            { unsigned bf[2] = {b2, b3}; mma_f16(oacc[1], ap, bf); }
            { unsigned bf[2] = {c0, c1}; mma_f16(oacc[2], ap, bf); }
            { unsigned bf[2] = {c2, c3}; mma_f16(oacc[3], ap, bf); }
        }
        __syncwarp();

        #pragma unroll
        for (int nt = 0; nt < 4; nt++) {
            const int c = nt * 8 + tg * 2;
            __half* opA = g_ao16 + ((size_t)win * NTOK + rb + g) * CDIM + hc + c;
            __half* opB = g_ao16 + ((size_t)win * NTOK + rb + 8 + g) * CDIM + hc + c;
            *reinterpret_cast<__half2*>(opA) =
                __floats2half2_rn(oacc[nt][0] * invA, oacc[nt][1] * invA);
            *reinterpret_cast<__half2*>(opB) =
                __floats2half2_rn(oacc[nt][2] * invB, oacc[nt][3] * invB);
        }
    }
}

// ---------------------------------------------------------------------------
// LayerNorm + residual, f16 y input (unchanged from R14)
// ---------------------------------------------------------------------------
__global__ void ln_add_kernel(const __half* __restrict__ y,
                              const float* __restrict__ g,
                              const float* __restrict__ b,
                              const float* __restrict__ xin,
                              float* __restrict__ xout,
                              __half* __restrict__ xh16,
                              int mode) {
    int w = (blockIdx.x * blockDim.x + threadIdx.x) >> 5;
    int lane = threadIdx.x & 31;
    if (w >= MTOK) return;
    size_t p;
    if (mode == 0) {
        p = (size_t)w;
    } else {
        int n = w % NTOK, win = w / NTOK;
        int l = win % NWW, t = win / NWW;
        int tz = t / 8, th = t % 8;
        int z1 = n / 72, h1 = (n % 72) / 12, w1 = n % 12;
        int zr = tz * 2 + z1, hr = th * 6 + h1, wr = l * 12 + w1;
        int z, hh, ww;
        if (mode == 2) { z = (zr + 7) & 7; hh = (hr + 45) % 48; ww = (wr + 186) % 192; }
        else           { z = zr; hh = hr; ww = wr; }
        p = ((size_t)z * 48 + hh) * 192 + ww;
    }
    const __half* yr = y + (size_t)w * CDIM;
    float v[6];
    float sum = 0.0f;
    #pragma unroll
    for (int i = 0; i < 3; i++) {
        const int c = lane * 2 + 64 * i;
        float2 f = __half22float2(*reinterpret_cast<const __half2*>(yr + c));
        v[2 * i] = f.x; v[2 * i + 1] = f.y;
        sum += f.x + f.y;
    }
    #pragma unroll
    for (int o = 16; o; o >>= 1) sum += __shfl_xor_sync(0xFFFFFFFFu, sum, o);
    float mu = sum * (1.0f / 192.0f);
    float var = 0.0f;
    #pragma unroll
    for (int i = 0; i < 6; i++) { float d = v[i] - mu; var += d * d; }
    #pragma unroll
    for (int o = 16; o; o >>= 1) var += __shfl_xor_sync(0xFFFFFFFFu, var, o);
    var *= (1.0f / 192.0f);
    float rs = rsqrtf(var + 1e-5f);
    const float* xi = xin + p * CDIM;
    float* xo = xout + p * CDIM;
    #pragma unroll
    for (int i = 0; i < 3; i++) {
        const int c = lane * 2 + 64 * i;
        const float2 x2 = *reinterpret_cast<const float2*>(xi + c);
        const float2 g2 = *reinterpret_cast<const float2*>(g + c);
        const float2 b2 = *reinterpret_cast<const float2*>(b + c);
        float o0 = x2.x + (v[2 * i]     - mu) * rs * g2.x + b2.x;
        float o1 = x2.y + (v[2 * i + 1] - mu) * rs * g2.y + b2.y;
        *reinterpret_cast<float2*>(xo + c) = make_float2(o0, o1);
        if (xh16)
            *reinterpret_cast<__half2*>(xh16 + p * CDIM + c) = __floats2half2_rn(o0, o1);
    }
}

extern "C" void kernel_launch(void* const* d_in, const int* in_sizes, int n_in,
                              void* d_out, int out_size) {
    const float* x_in       = (const float*)d_in[0];
    const float* qkv_w      = (const float*)d_in[1];
    const float* qkv_b      = (const float*)d_in[2];
    const float* proj_w     = (const float*)d_in[3];
    const float* proj_b     = (const float*)d_in[4];
    const float* bias_table = (const float*)d_in[5];
    const float* n1_g       = (const float*)d_in[6];
    const float* n1_b       = (const float*)d_in[7];
    const float* n2_g       = (const float*)d_in[8];
    const float* n2_b       = (const float*)d_in[9];
    const float* w1         = (const float*)d_in[10];
    const float* b1         = (const float*)d_in[11];
    const float* w2         = (const float*)d_in[12];
    const float* b2         = (const float*)d_in[13];
    // d_in[14..16] = Z,H,W scalars (fixed 8,48,192)

    float  *gx;
    __half *gxh, *gqkv, *gao, *gh, *gwt;
    cudaGetSymbolAddress((void**)&gx,   g_x);
    cudaGetSymbolAddress((void**)&gxh,  g_xh16);
    cudaGetSymbolAddress((void**)&gqkv, g_qkv16);
    cudaGetSymbolAddress((void**)&gao,  g_ao16);
    cudaGetSymbolAddress((void**)&gh,   g_h16);
    cudaGetSymbolAddress((void**)&gwt,  g_wt16);

    cudaFuncSetAttribute(hgemm_resA_kernel<0,1>, cudaFuncAttributeMaxDynamicSharedMemorySize, RESA_SMEM);
    cudaFuncSetAttribute(hgemm_resA_kernel<0,0>, cudaFuncAttributeMaxDynamicSharedMemorySize, RESA_SMEM);
    cudaFuncSetAttribute(hgemm_resA_kernel<1,0>, cudaFuncAttributeMaxDynamicSharedMemorySize, RESA_SMEM);
    cudaFuncSetAttribute(hgemm_kernel<0>, cudaFuncAttributeMaxDynamicSharedMemorySize, GEMM_SMEM16);
    cudaFuncSetAttribute(attn_f16_kernel, cudaFuncAttributeMaxDynamicSharedMemorySize, ATTN_SMEM16);

    transpose_all_kernel<<<864, dim3(32, 8)>>>(qkv_w, proj_w, w1, w2);
    cvt_f16_kernel<<<(MTOK * CDIM + 255) / 256, 256>>>(x_in, gxh, MTOK * CDIM);
    {
        size_t total = (size_t)2 * TWIN * NHEAD * NTOK * NTOK;
        biasmask_kernel<<<(unsigned)((total + 255) / 256), 256>>>(bias_table);
    }

    for (int L = 0; L < 2; L++) {
        const float* xsrc = (L == 0) ? x_in : gx;

        // QKV (fused window gather), resident-A: 9 N-chunks
        hgemm_resA_kernel<0,1><<<MTOK / 128, 256, RESA_SMEM>>>(
            gxh, gwt + WQ_OFF + (size_t)L * CDIM * QKVN, qkv_b + (size_t)L * QKVN,
            gqkv, QKVN / 64, QKVN, L);

        attn_f16_kernel<<<dim3(NWIN, NHEAD), 128, ATTN_SMEM16>>>(L);

        // proj, resident-A: 3 N-chunks -> g_h16
        hgemm_resA_kernel<0,0><<<MTOK / 128, 256, RESA_SMEM>>>(
            gao, gwt + WP_OFF + (size_t)L * CDIM * CDIM, proj_b + (size_t)L * CDIM,
            gh, CDIM / 64, CDIM, 0);

        // x = xsrc + LN(un-window(proj_out)); + f16 copy for next GEMM
        ln_add_kernel<<<(MTOK * 32 + 255) / 256, 256>>>(
            gh, n1_g + (size_t)L * CDIM, n1_b + (size_t)L * CDIM,
            xsrc, gx, gxh, L ? 2 : 1);

        // MLP up (gelu), resident-A: 12 N-chunks -> g_h16
        hgemm_resA_kernel<1,0><<<MTOK / 128, 256, RESA_SMEM>>>(
            gxh, gwt + W1_OFF + (size_t)L * CDIM * FFN, b1 + (size_t)L * FFN,
            gh, FFN / 64, FFN, 0);

        // MLP down (K=768), streaming kernel -> g_qkv16
        hgemm_kernel<0><<<dim3(CDIM / 64, MTOK / 128), 256, GEMM_SMEM16>>>(
            gh, gwt + W2_OFF + (size_t)L * FFN * CDIM, b2 + (size_t)L * CDIM,
            gqkv, FFN, CDIM);

        // x = x + LN(mlp_out); final layer writes straight to d_out
        float*  xo  = (L == 1) ? (float*)d_out : gx;
        __half* xho = (L == 1) ? (__half*)nullptr : gxh;
        ln_add_kernel<<<(MTOK * 32 + 255) / 256, 256>>>(
            gqkv, n2_g + (size_t)L * CDIM, n2_b + (size_t)L * CDIM,
            gx, xo, xho, 0);
    }
}

// round 16
// speedup vs baseline: 1.0203x; 1.0203x over previous
#include <cuda_runtime.h>
#include <cuda_fp16.h>
#include <math.h>

#define MTOK   73728
#define CDIM   192
#define NHEAD  6
#define HD     32
#define NTOK   144
#define NWIN   512
#define TWIN   32
#define NWW    16
#define NB     3312
#define QKVN   576
#define FFN    768

// fp32 buffers (residual stream, bias table)
__device__ float  g_x   [(size_t)MTOK * CDIM];
__device__ float  g_bm  [(size_t)2 * TWIN * NHEAD * NTOK * NTOK];
// f16 activation buffers
__device__ __half g_xh16 [(size_t)MTOK * CDIM];
__device__ __half g_qkv16[(size_t)MTOK * QKVN];   // QKV out; also MLP-down out
__device__ __half g_ao16 [(size_t)MTOK * CDIM];
__device__ __half g_h16  [(size_t)MTOK * FFN];    // MLP hidden; also proj out
// f16 transposed weights [N][K]: qkv | proj | w1 | w2 (both layers)
#define WQ_OFF 0
#define WP_OFF 221184
#define W1_OFF 294912
#define W2_OFF 589824
__device__ __half g_wt16[884736];

// ---------------------------------------------------------------------------
// helpers
// ---------------------------------------------------------------------------
__device__ __forceinline__ void mma_f16(float* d, const unsigned* a, const unsigned* b) {
    asm volatile(
        "mma.sync.aligned.m16n8k16.row.col.f32.f16.f16.f32 "
        "{%0,%1,%2,%3}, {%4,%5,%6,%7}, {%8,%9}, {%0,%1,%2,%3};\n"
        : "+f"(d[0]), "+f"(d[1]), "+f"(d[2]), "+f"(d[3])
        : "r"(a[0]), "r"(a[1]), "r"(a[2]), "r"(a[3]),
          "r"(b[0]), "r"(b[1]));
}

__device__ __forceinline__ void ldsm_x4(unsigned& r0, unsigned& r1,
                                        unsigned& r2, unsigned& r3, unsigned a) {
    asm volatile("ldmatrix.sync.aligned.m8n8.x4.shared.b16 {%0,%1,%2,%3}, [%4];"
                 : "=r"(r0), "=r"(r1), "=r"(r2), "=r"(r3) : "r"(a));
}
#define STSM_X2(addr, r0, r1) \
    asm volatile("stmatrix.sync.aligned.m8n8.x2.shared.b16 [%0], {%1,%2};" \
                 :: "r"(addr), "r"(r0), "r"(r1))

__device__ __forceinline__ unsigned h2u(float a, float b) {
    __half2 h = __floats2half2_rn(a, b);
    return reinterpret_cast<unsigned&>(h);
}

__device__ __forceinline__ unsigned smaddr(const void* p) {
    return (unsigned)__cvta_generic_to_shared(p);
}
#define CPA16(dst, src) asm volatile("cp.async.cg.shared.global [%0], [%1], 16;" :: "r"(dst), "l"(src))
#define CPCOMMIT()      asm volatile("cp.async.commit_group;")
#define CPWAIT1()       asm volatile("cp.async.wait_group 1;")

__device__ __forceinline__ float gelu_exact(float v) {
    return 0.5f * v * (1.0f + erff(v * 0.70710678118654752f));
}

// ---------------------------------------------------------------------------
// Batched prep: all 8 weight transposes (fp32 [K][N] -> f16 [N][K]); 864 tiles.
// ---------------------------------------------------------------------------
__global__ void transpose_all_kernel(const float* __restrict__ qkv_w,
                                     const float* __restrict__ proj_w,
                                     const float* __restrict__ w1,
                                     const float* __restrict__ w2) {
    __shared__ float t[32][33];
    int idx = blockIdx.x;
    const int layer = idx / 432;
    int r = idx % 432;

    const float* src;
    __half* dst;
    int K, N, kt, nt;
    if (r < 108) {
        K = CDIM; N = QKVN;
        kt = r / 18; nt = r % 18;
        src = qkv_w + (size_t)layer * CDIM * QKVN;
        dst = g_wt16 + WQ_OFF + (size_t)layer * CDIM * QKVN;
    } else if (r < 144) {
        r -= 108; K = CDIM; N = CDIM;
        kt = r / 6; nt = r % 6;
        src = proj_w + (size_t)layer * CDIM * CDIM;
        dst = g_wt16 + WP_OFF + (size_t)layer * CDIM * CDIM;
    } else if (r < 288) {
        r -= 144; K = CDIM; N = FFN;
        kt = r / 24; nt = r % 24;
        src = w1 + (size_t)layer * CDIM * FFN;
        dst = g_wt16 + W1_OFF + (size_t)layer * CDIM * FFN;
    } else {
        r -= 288; K = FFN; N = CDIM;
        kt = r / 6; nt = r % 6;
        src = w2 + (size_t)layer * FFN * CDIM;
        dst = g_wt16 + W2_OFF + (size_t)layer * FFN * CDIM;
    }

    const int n0 = nt * 32, k0 = kt * 32;
    const int tx = threadIdx.x, ty = threadIdx.y;
    #pragma unroll
    for (int i = 0; i < 32; i += 8)
        t[ty + i][tx] = src[(size_t)(k0 + ty + i) * N + n0 + tx];
    __syncthreads();
    #pragma unroll
    for (int i = 0; i < 32; i += 8)
        dst[(size_t)(n0 + ty + i) * K + k0 + tx] = __float2half_rn(t[tx][ty + i]);
}

__global__ void cvt_f16_kernel(const float* __restrict__ src,
                               __half* __restrict__ dst, int n) {
    int i = blockIdx.x * blockDim.x + threadIdx.x;
    if (i < n) dst[i] = __float2half_rn(src[i]);
}

// ---------------------------------------------------------------------------
// Dense (relative-position bias + shift mask)
// ---------------------------------------------------------------------------
__global__ void biasmask_kernel(const float* __restrict__ table) {
    size_t idx = (size_t)blockIdx.x * blockDim.x + threadIdx.x;
    size_t total = (size_t)2 * TWIN * NHEAD * NTOK * NTOK;
    if (idx >= total) return;
    int m = idx % NTOK; size_t r = idx / NTOK;
    int n = r % NTOK;   r /= NTOK;
    int head = r % NHEAD; r /= NHEAD;
    int t = r % TWIN;   int L = (int)(r / TWIN);
    int z1 = n / 72, h1 = (n % 72) / 12, w1 = n % 12;
    int z2 = m / 72, h2 = (m % 72) / 12, w2 = m % 12;
    int pos = 828 * (z1 + 2 * z2) + 23 * (h1 + 6 * h2) + (w1 - w2 + 11);
    float v = table[(((size_t)L * NB + pos) * TWIN + t) * NHEAD + head];
    if (L == 1) {
        int tz = t / 8, th = t % 8;
        int idn = (((tz * 2 + z1) >= 1) ? 2 : 0) + (((th * 6 + h1) >= 3) ? 1 : 0);
        int idm = (((tz * 2 + z2) >= 1) ? 2 : 0) + (((th * 6 + h2) >= 3) ? 1 : 0);
        if (idn != idm) v += -10000.0f;
    }
    g_bm[idx] = v;
}

// ---------------------------------------------------------------------------
// Streaming f16 GEMM (R11/R14, proven): m16n8k16, ldmatrix, 3-stage cp.async,
// one __syncthreads per iteration. BM=128, BN=64, BK=32, 256 thr / 8 warps.
// ---------------------------------------------------------------------------
#define ASTG16 (128 * 40)
#define BSTG16 (64 * 40)
#define GEMM_SMEM16 ((3 * ASTG16 + 3 * BSTG16) * 2)   // 46080 B

template <int EPI, int GATHER>
__global__ void __launch_bounds__(256, 3)
hgemm_kernel(const __half* __restrict__ A,
             const __half* __restrict__ B,
             const float* __restrict__ bias,
             __half* __restrict__ C16,
             int K, int Nn, int rolled) {
    extern __shared__ __half hsm[];
    __half* As = hsm;
    __half* Bs = hsm + 3 * ASTG16;

    const int tid  = threadIdx.x;
    const int lane = tid & 31;
    const int wid  = tid >> 5;
    const int wm   = wid >> 1;
    const int wn   = wid & 1;
    const int g    = lane >> 2;
    const int tg   = lane & 3;
    const int m0   = blockIdx.y * 128;
    const int n0   = blockIdx.x * 64;

    const unsigned lrow = lane & 7;
    const unsigned lsel = (lane >> 3) & 1;
    const unsigned lhi  = lane >> 4;
    const unsigned aoff = ((lrow + lsel * 8) * 40 + lhi * 8) * 2;
    const unsigned boff = ((lrow + lhi * 8) * 40 + lsel * 8) * 2;

    const int arow = tid >> 1;
    const int ac0  = (tid & 1) * 2;
    const int brow = tid >> 2;
    const int bchk = tid & 3;

    size_t arowp;
    {
        int r = m0 + arow;
        if (GATHER) {
            int n = r % NTOK, win = r / NTOK;
            int l = win % NWW, t = win / NWW;
            int tz = t / 8, th = t % 8;
            int z1 = n / 72, h1 = (n % 72) / 12, w1 = n % 12;
            int zr = tz * 2 + z1, hr = th * 6 + h1, wr = l * 12 + w1;
            int z, hh, ww;
            if (rolled) { z = (zr + 7) & 7; hh = (hr + 45) % 48; ww = (wr + 186) % 192; }
            else        { z = zr; hh = hr; ww = wr; }
            arowp = ((size_t)z * 48 + hh) * 192 + ww;
        } else {
            arowp = (size_t)r;
        }
    }
    const __half* aSrc = A + arowp * K;
    const __half* bSrc = B + (size_t)(n0 + brow) * K;

    float acc[2][4][4];
    #pragma unroll
    for (int mt = 0; mt < 2; mt++)
        #pragma unroll
        for (int nt = 0; nt < 4; nt++)
            #pragma unroll
            for (int i = 0; i < 4; i++) acc[mt][nt][i] = 0.0f;

    #pragma unroll
    for (int s = 0; s < 2; s++) {
        __half* as = As + s * ASTG16;
        __half* bs = Bs + s * BSTG16;
        const int k0 = s * 32;
        #pragma unroll
        for (int j = 0; j < 2; j++)
            CPA16(smaddr(as + arow * 40 + (ac0 + j) * 8), aSrc + k0 + (ac0 + j) * 8);
        CPA16(smaddr(bs + brow * 40 + bchk * 8), bSrc + k0 + bchk * 8);
        CPCOMMIT();
    }

    const int iters = K >> 5;
    int cur = 0;
    for (int it = 0; it < iters; it++) {
        CPWAIT1();
        __syncthreads();

        const int k0n = (it + 2) << 5;
        if (k0n < K) {
            const int stg = (cur + 2) % 3;
            __half* asw = As + stg * ASTG16;
            __half* bsw = Bs + stg * BSTG16;
            #pragma unroll
            for (int j = 0; j < 2; j++)
                CPA16(smaddr(asw + arow * 40 + (ac0 + j) * 8), aSrc + k0n + (ac0 + j) * 8);
            CPA16(smaddr(bsw + brow * 40 + bchk * 8), bSrc + k0n + bchk * 8);
        }
        CPCOMMIT();

        const __half* as = As + cur * ASTG16;
        const __half* bs = Bs + cur * BSTG16;
        const unsigned aB = smaddr(as) + (unsigned)(wm * 32 * 40) * 2 + aoff;
        const unsigned bB = smaddr(bs) + (unsigned)(wn * 32 * 40) * 2 + boff;
        #pragma unroll
        for (int kk2 = 0; kk2 < 2; kk2++) {
            unsigned af[2][4], bf[4][2];
            ldsm_x4(af[0][0], af[0][1], af[0][2], af[0][3], aB + kk2 * 32);
            ldsm_x4(af[1][0], af[1][1], af[1][2], af[1][3], aB + 1280 + kk2 * 32);
            ldsm_x4(bf[0][0], bf[0][1], bf[1][0], bf[1][1], bB + kk2 * 32);
            ldsm_x4(bf[2][0], bf[2][1], bf[3][0], bf[3][1], bB + 1280 + kk2 * 32);
            #pragma unroll
            for (int mt = 0; mt < 2; mt++)
                #pragma unroll
                for (int nt = 0; nt < 4; nt++)
                    mma_f16(acc[mt][nt], af[mt], bf[nt]);
        }
        cur = (cur + 1) % 3;
    }

    #pragma unroll
    for (int mt = 0; mt < 2; mt++) {
        int r0 = m0 + wm * 32 + mt * 16 + g;
        #pragma unroll
        for (int nt = 0; nt < 4; nt++) {
            int c = n0 + wn * 32 + nt * 8 + tg * 2;
            float b0 = bias[c], b1 = bias[c + 1];
            float v0 = acc[mt][nt][0] + b0;
            float v1 = acc[mt][nt][1] + b1;
            float v2 = acc[mt][nt][2] + b0;
            float v3 = acc[mt][nt][3] + b1;
            if (EPI == 1) {
                v0 = gelu_exact(v0); v1 = gelu_exact(v1);
                v2 = gelu_exact(v2); v3 = gelu_exact(v3);
            }
            *reinterpret_cast<__half2*>(C16 + (size_t)r0 * Nn + c) =
                __floats2half2_rn(v0, v1);
            *reinterpret_cast<__half2*>(C16 + (size_t)(r0 + 8) * Nn + c) =
                __floats2half2_rn(v2, v3);
        }
    }
}

// ---------------------------------------------------------------------------
// f16 tensor-core window attention — 160 threads / 5 warps.
// 9 row-tiles over 5 warps -> max 2 tiles per warp (was 3 over 4 warps).
// Per-tile math identical to the proven kernel (bit-exact).
// ---------------------------------------------------------------------------
#define KS16_S 40
#define VT16_S 152
#define SCR16_S 152
#define ATTN_NW 5
#define ATTN_SMEM16 ((NTOK * KS16_S + HD * VT16_S + ATTN_NW * 16 * SCR16_S) * 2) // 45568 B

__global__ void __launch_bounds__(160, 3) attn_f16_kernel(int L) {
    const int win  = blockIdx.x;
    const int head = blockIdx.y;
    const int t    = win >> 4;
    extern __shared__ __half smh[];
    __half* ks  = smh;
    __half* vsT = ks + NTOK * KS16_S;
    __half* scr = vsT + HD * VT16_S;

    const int tid  = threadIdx.x;
    const int lane = tid & 31;
    const int wid  = tid >> 5;
    const int g    = lane >> 2;
    const int tg   = lane & 3;

    const unsigned lrow = lane & 7;
    const unsigned lsel = (lane >> 3) & 1;
    const unsigned lhi  = lane >> 4;
    const unsigned kboff = ((lrow + lhi * 8) * KS16_S + lsel * 8) * 2;
    const unsigned paoff = ((lrow + lsel * 8) * SCR16_S + lhi * 8) * 2;
    const unsigned vboff = ((lrow + lhi * 8) * VT16_S + lsel * 8) * 2;

    const __half* base = g_qkv16 + (size_t)win * NTOK * QKVN;
    const int hc = head * HD;
    for (int idx = tid; idx < NTOK * 4; idx += 160) {
        int row = idx >> 2, c = idx & 3;
        *reinterpret_cast<uint4*>(&ks[row * KS16_S + c * 8]) =
            *reinterpret_cast<const uint4*>(base + (size_t)row * QKVN + CDIM + hc + c * 8);
        uint4 v4 = *reinterpret_cast<const uint4*>(base + (size_t)row * QKVN + 2 * CDIM + hc + c * 8);
        const __half* hv = reinterpret_cast<const __half*>(&v4);
        #pragma unroll
        for (int j = 0; j < 8; j++)
            vsT[(c * 8 + j) * VT16_S + row] = hv[j];
    }
    __syncthreads();

    const float* bmb = g_bm + (((size_t)L * TWIN + t) * NHEAD + head) * NTOK * NTOK;
    __half* wscr = scr + wid * 16 * SCR16_S;
    const unsigned kbase  = smaddr(ks) + kboff;
    const unsigned pbase  = smaddr(wscr) + paoff;
    const unsigned vbase  = smaddr(vsT) + vboff;
    const unsigned stbase = smaddr(wscr) + (unsigned)((lane & 15) * SCR16_S) * 2;
    const float sc = 0.17677669529663687f;

    for (int mt = wid; mt < 9; mt += ATTN_NW) {
        const int rb = mt * 16;

        const __half* qA = g_qkv16 + (size_t)(win * NTOK + rb + g) * QKVN + hc;
        const __half* qB = g_qkv16 + (size_t)(win * NTOK + rb + 8 + g) * QKVN + hc;
        unsigned aq[2][4];
        #pragma unroll
        for (int kk2 = 0; kk2 < 2; kk2++) {
            const int kk = kk2 * 16 + 2 * tg;
            aq[kk2][0] = *reinterpret_cast<const unsigned*>(qA + kk);
            aq[kk2][1] = *reinterpret_cast<const unsigned*>(qB + kk);
            aq[kk2][2] = *reinterpret_cast<const unsigned*>(qA + kk + 8);
            aq[kk2][3] = *reinterpret_cast<const unsigned*>(qB + kk + 8);
        }

        float sacc[18][4];
        #pragma unroll
        for (int ntp = 0; ntp < 9; ntp++) {
            float* s0 = sacc[2 * ntp];
            float* s1 = sacc[2 * ntp + 1];
            #pragma unroll
            for (int i = 0; i < 4; i++) { s0[i] = 0.0f; s1[i] = 0.0f; }
            #pragma unroll
            for (int kk2 = 0; kk2 < 2; kk2++) {
                unsigned b0, b1, b2, b3;
                ldsm_x4(b0, b1, b2, b3, kbase + ntp * (16 * KS16_S * 2) + kk2 * 32);
                unsigned bfa[2] = {b0, b1}, bfb[2] = {b2, b3};
                mma_f16(s0, aq[kk2], bfa);
                mma_f16(s1, aq[kk2], bfb);
            }
            #pragma unroll
            for (int h = 0; h < 2; h++) {
                float* sv = h ? s1 : s0;
                const int cb = (2 * ntp + h) * 8;
                const float2 bA = *reinterpret_cast<const float2*>(
                    bmb + (size_t)(rb + g) * NTOK + cb + tg * 2);
                const float2 bB = *reinterpret_cast<const float2*>(
                    bmb + (size_t)(rb + 8 + g) * NTOK + cb + tg * 2);
                sv[0] = fmaf(sv[0], sc, bA.x);
                sv[1] = fmaf(sv[1], sc, bA.y);
                sv[2] = fmaf(sv[2], sc, bB.x);
                sv[3] = fmaf(sv[3], sc, bB.y);
            }
        }

        float mxA = -1e30f, mxB = -1e30f;
        #pragma unroll
        for (int nt = 0; nt < 18; nt++) {
            mxA = fmaxf(mxA, fmaxf(sacc[nt][0], sacc[nt][1]));
            mxB = fmaxf(mxB, fmaxf(sacc[nt][2], sacc[nt][3]));
        }
        #pragma unroll
        for (int o = 1; o <= 2; o <<= 1) {
            mxA = fmaxf(mxA, __shfl_xor_sync(0xFFFFFFFFu, mxA, o));
            mxB = fmaxf(mxB, __shfl_xor_sync(0xFFFFFFFFu, mxB, o));
        }
        float smA = 0.0f, smB = 0.0f;
        #pragma unroll
        for (int nt = 0; nt < 18; nt++) {
            sacc[nt][0] = __expf(sacc[nt][0] - mxA);
            sacc[nt][1] = __expf(sacc[nt][1] - mxA);
            sacc[nt][2] = __expf(sacc[nt][2] - mxB);
            sacc[nt][3] = __expf(sacc[nt][3] - mxB);
            smA += sacc[nt][0] + sacc[nt][1];
            smB += sacc[nt][2] + sacc[nt][3];
        }
        #pragma unroll
        for (int o = 1; o <= 2; o <<= 1) {
            smA += __shfl_xor_sync(0xFFFFFFFFu, smA, o);
            smB += __shfl_xor_sync(0xFFFFFFFFu, smB, o);
        }
        const float invA = 1.0f / smA;
        const float invB = 1.0f / smB;

        #pragma unroll
        for (int nt = 0; nt < 18; nt++) {
            unsigned r0 = h2u(sacc[nt][0], sacc[nt][1]);
            unsigned r1 = h2u(sacc[nt][2], sacc[nt][3]);
            STSM_X2(stbase + nt * 16, r0, r1);
        }
        __syncwarp();

        float oacc[4][4];
        #pragma unroll
        for (int nt = 0; nt < 4; nt++)
            oacc[nt][0] = oacc[nt][1] = oacc[nt][2] = oacc[nt][3] = 0.0f;
        #pragma unroll
        for (int kk = 0; kk < 9; kk++) {
            unsigned ap[4];
            ldsm_x4(ap[0], ap[1], ap[2], ap[3], pbase + kk * 32);
            unsigned b0, b1, b2, b3, c0, c1, c2, c3;
            ldsm_x4(b0, b1, b2, b3, vbase + kk * 32);
            ldsm_x4(c0, c1, c2, c3, vbase + (16 * VT16_S * 2) + kk * 32);
            { unsigned bf[2] = {b0, b1}; mma_f16(oacc[0], ap, bf); }
            { unsigned bf[2] = {b2, b3}; mma_f16(oacc[1], ap, bf); }
            { unsigned bf[2] = {c0, c1}; mma_f16(oacc[2], ap, bf); }
            { unsigned bf[2] = {c2, c3}; mma_f16(oacc[3], ap, bf); }
        }
        __syncwarp();

        #pragma unroll
        for (int nt = 0; nt < 4; nt++) {
            const int c = nt * 8 + tg * 2;
            __half* opA = g_ao16 + ((size_t)win * NTOK + rb + g) * CDIM + hc + c;
            __half* opB = g_ao16 + ((size_t)win * NTOK + rb + 8 + g) * CDIM + hc + c;
            *reinterpret_cast<__half2*>(opA) =
                __floats2half2_rn(oacc[nt][0] * invA, oacc[nt][1] * invA);
            *reinterpret_cast<__half2*>(opB) =
                __floats2half2_rn(oacc[nt][2] * invB, oacc[nt][3] * invB);
        }
    }
}

// ---------------------------------------------------------------------------
// LayerNorm + residual, f16 y input (unchanged from R14)
// ---------------------------------------------------------------------------
__global__ void ln_add_kernel(const __half* __restrict__ y,
                              const float* __restrict__ g,
                              const float* __restrict__ b,
                              const float* __restrict__ xin,
                              float* __restrict__ xout,
                              __half* __restrict__ xh16,
                              int mode) {
    int w = (blockIdx.x * blockDim.x + threadIdx.x) >> 5;
    int lane = threadIdx.x & 31;
    if (w >= MTOK) return;
    size_t p;
    if (mode == 0) {
        p = (size_t)w;
    } else {
        int n = w % NTOK, win = w / NTOK;
        int l = win % NWW, t = win / NWW;
        int tz = t / 8, th = t % 8;
        int z1 = n / 72, h1 = (n % 72) / 12, w1 = n % 12;
        int zr = tz * 2 + z1, hr = th * 6 + h1, wr = l * 12 + w1;
        int z, hh, ww;
        if (mode == 2) { z = (zr + 7) & 7; hh = (hr + 45) % 48; ww = (wr + 186) % 192; }
        else           { z = zr; hh = hr; ww = wr; }
        p = ((size_t)z * 48 + hh) * 192 + ww;
    }
    const __half* yr = y + (size_t)w * CDIM;
    float v[6];
    float sum = 0.0f;
    #pragma unroll
    for (int i = 0; i < 3; i++) {
        const int c = lane * 2 + 64 * i;
        float2 f = __half22float2(*reinterpret_cast<const __half2*>(yr + c));
        v[2 * i] = f.x; v[2 * i + 1] = f.y;
        sum += f.x + f.y;
    }
    #pragma unroll
    for (int o = 16; o; o >>= 1) sum += __shfl_xor_sync(0xFFFFFFFFu, sum, o);
    float mu = sum * (1.0f / 192.0f);
    float var = 0.0f;
    #pragma unroll
    for (int i = 0; i < 6; i++) { float d = v[i] - mu; var += d * d; }
    #pragma unroll
    for (int o = 16; o; o >>= 1) var += __shfl_xor_sync(0xFFFFFFFFu, var, o);
    var *= (1.0f / 192.0f);
    float rs = rsqrtf(var + 1e-5f);
    const float* xi = xin + p * CDIM;
    float* xo = xout + p * CDIM;
    #pragma unroll
    for (int i = 0; i < 3; i++) {
        const int c = lane * 2 + 64 * i;
        const float2 x2 = *reinterpret_cast<const float2*>(xi + c);
        const float2 g2 = *reinterpret_cast<const float2*>(g + c);
        const float2 b2 = *reinterpret_cast<const float2*>(b + c);
        float o0 = x2.x + (v[2 * i]     - mu) * rs * g2.x + b2.x;
        float o1 = x2.y + (v[2 * i + 1] - mu) * rs * g2.y + b2.y;
        *reinterpret_cast<float2*>(xo + c) = make_float2(o0, o1);
        if (xh16)
            *reinterpret_cast<__half2*>(xh16 + p * CDIM + c) = __floats2half2_rn(o0, o1);
    }
}

extern "C" void kernel_launch(void* const* d_in, const int* in_sizes, int n_in,
                              void* d_out, int out_size) {
    const float* x_in       = (const float*)d_in[0];
    const float* qkv_w      = (const float*)d_in[1];
    const float* qkv_b      = (const float*)d_in[2];
    const float* proj_w     = (const float*)d_in[3];
    const float* proj_b     = (const float*)d_in[4];
    const float* bias_table = (const float*)d_in[5];
    const float* n1_g       = (const float*)d_in[6];
    const float* n1_b       = (const float*)d_in[7];
    const float* n2_g       = (const float*)d_in[8];
    const float* n2_b       = (const float*)d_in[9];
    const float* w1         = (const float*)d_in[10];
    const float* b1         = (const float*)d_in[11];
    const float* w2         = (const float*)d_in[12];
    const float* b2         = (const float*)d_in[13];
    // d_in[14..16] = Z,H,W scalars (fixed 8,48,192)

    float  *gx;
    __half *gxh, *gqkv, *gao, *gh, *gwt;
    cudaGetSymbolAddress((void**)&gx,   g_x);
    cudaGetSymbolAddress((void**)&gxh,  g_xh16);
    cudaGetSymbolAddress((void**)&gqkv, g_qkv16);
    cudaGetSymbolAddress((void**)&gao,  g_ao16);
    cudaGetSymbolAddress((void**)&gh,   g_h16);
    cudaGetSymbolAddress((void**)&gwt,  g_wt16);

    cudaFuncSetAttribute(hgemm_kernel<0,1>, cudaFuncAttributeMaxDynamicSharedMemorySize, GEMM_SMEM16);
    cudaFuncSetAttribute(hgemm_kernel<0,0>, cudaFuncAttributeMaxDynamicSharedMemorySize, GEMM_SMEM16);
    cudaFuncSetAttribute(hgemm_kernel<1,0>, cudaFuncAttributeMaxDynamicSharedMemorySize, GEMM_SMEM16);
    cudaFuncSetAttribute(attn_f16_kernel, cudaFuncAttributeMaxDynamicSharedMemorySize, ATTN_SMEM16);

    transpose_all_kernel<<<864, dim3(32, 8)>>>(qkv_w, proj_w, w1, w2);
    cvt_f16_kernel<<<(MTOK * CDIM + 255) / 256, 256>>>(x_in, gxh, MTOK * CDIM);
    {
        size_t total = (size_t)2 * TWIN * NHEAD * NTOK * NTOK;
        biasmask_kernel<<<(unsigned)((total + 255) / 256), 256>>>(bias_table);
    }

    for (int L = 0; L < 2; L++) {
        const float* xsrc = (L == 0) ? x_in : gx;

        // QKV (fused window gather), f16 out -> g_qkv16
        hgemm_kernel<0,1><<<dim3(QKVN / 64, MTOK / 128), 256, GEMM_SMEM16>>>(
            gxh, gwt + WQ_OFF + (size_t)L * CDIM * QKVN, qkv_b + (size_t)L * QKVN,
            gqkv, CDIM, QKVN, L);

        attn_f16_kernel<<<dim3(NWIN, NHEAD), 160, ATTN_SMEM16>>>(L);

        // proj: f16 in, f16 out -> g_h16 (free until MLP-up rewrites it)
        hgemm_kernel<0,0><<<dim3(CDIM / 64, MTOK / 128), 256, GEMM_SMEM16>>>(
            gao, gwt + WP_OFF + (size_t)L * CDIM * CDIM, proj_b + (size_t)L * CDIM,
            gh, CDIM, CDIM, 0);

        // x = xsrc + LN(un-window(proj_out)); + f16 copy for next GEMM
        ln_add_kernel<<<(MTOK * 32 + 255) / 256, 256>>>(
            gh, n1_g + (size_t)L * CDIM, n1_b + (size_t)L * CDIM,
            xsrc, gx, gxh, L ? 2 : 1);

        // MLP up: gelu, f16 out -> g_h16
        hgemm_kernel<1,0><<<dim3(FFN / 64, MTOK / 128), 256, GEMM_SMEM16>>>(
            gxh, gwt + W1_OFF + (size_t)L * CDIM * FFN, b1 + (size_t)L * FFN,
            gh, CDIM, FFN, 0);

        // MLP down: f16 in, f16 out -> g_qkv16 (free; rewritten by next QKV)
        hgemm_kernel<0,0><<<dim3(CDIM / 64, MTOK / 128), 256, GEMM_SMEM16>>>(
            gh, gwt + W2_OFF + (size_t)L * FFN * CDIM, b2 + (size_t)L * CDIM,
            gqkv, FFN, CDIM, 0);

        // x = x + LN(mlp_out); final layer writes straight to d_out
        float*  xo  = (L == 1) ? (float*)d_out : gx;
        __half* xho = (L == 1) ? (__half*)nullptr : gxh;
        ln_add_kernel<<<(MTOK * 32 + 255) / 256, 256>>>(
            gqkv, n2_g + (size_t)L * CDIM, n2_b + (size_t)L * CDIM,
            gx, xo, xho, 0);
    }
}